// round 11
// baseline (speedup 1.0000x reference)
#include <cuda_runtime.h>
#include <cuda_fp16.h>

#define NB 128
#define NB3 (NB * NB * NB)

// y-pair table: P[ix][iy][iz] = { G(ix,iy,iz) 4xfp16, G(ix,min(iy+1,127),iz) 4xfp16 }
// 16 B/entry, 33.5 MB -> L2-resident. Built with evict_last stores so the dirty
// lines stay in L2 for interp and write back lazily during the interp window.
__device__ uint4 g_ypairs[NB3];

__device__ __forceinline__ unsigned long long make_evict_last_policy()
{
    unsigned long long pol;
    asm("createpolicy.fractional.L2::evict_last.b64 %0, 1.0;" : "=l"(pol));
    return pol;
}

__device__ __forceinline__ void stg_pin(uint4* p, uint4 v, unsigned long long pol)
{
    asm volatile("st.global.L2::cache_hint.v4.u32 [%0], {%1,%2,%3,%4}, %5;"
                 :: "l"(p), "r"(v.x), "r"(v.y), "r"(v.z), "r"(v.w), "l"(pol)
                 : "memory");
}

__device__ __forceinline__ uint4 ldg_pin(const uint4* p, unsigned long long pol)
{
    uint4 v;
    asm("ld.global.nc.L2::cache_hint.v4.u32 {%0,%1,%2,%3}, [%4], %5;"
        : "=r"(v.x), "=r"(v.y), "=r"(v.z), "=r"(v.w)
        : "l"(p), "l"(pol));
    return v;
}

__device__ __forceinline__ uint2 pack_h4(float4 v)
{
    __half2 h0 = __floats2half2_rn(v.x, v.y);
    __half2 h1 = __floats2half2_rn(v.z, v.w);
    uint2 r;
    r.x = *reinterpret_cast<const unsigned int*>(&h0);
    r.y = *reinterpret_cast<const unsigned int*>(&h1);
    return r;
}

__global__ __launch_bounds__(256)
void build_ypairs_kernel(const float4* __restrict__ grid)
{
    int idx = blockIdx.x * blockDim.x + threadIdx.x;
    if (idx >= NB3) return;

    int iy = (idx >> 7) & (NB - 1);
    int dy = (iy < NB - 1) ? NB : 0;

    float4 a = grid[idx];        // (ix, iy,   iz)
    float4 b = grid[idx + dy];   // (ix, iy+1, iz) clamped; L2-hit via block locality

    uint2 pa = pack_h4(a);
    uint2 pb = pack_h4(b);

    uint4 v;
    v.x = pa.x; v.y = pa.y; v.z = pb.x; v.w = pb.y;

    unsigned long long pol = make_evict_last_policy();
    stg_pin(&g_ypairs[idx], v, pol);   // keep dirty line in L2; defer writeback
}

// y-lerp of one entry: corner_y0*wy0 + corner_y1*wy1
__device__ __forceinline__ float4 ylerp(uint4 p, float wy0, float wy1)
{
    float2 axy = __half22float2(*reinterpret_cast<const __half2*>(&p.x));
    float2 azw = __half22float2(*reinterpret_cast<const __half2*>(&p.y));
    float2 bxy = __half22float2(*reinterpret_cast<const __half2*>(&p.z));
    float2 bzw = __half22float2(*reinterpret_cast<const __half2*>(&p.w));

    float4 r;
    r.x = fmaf(wy1, bxy.x, wy0 * axy.x);
    r.y = fmaf(wy1, bxy.y, wy0 * axy.y);
    r.z = fmaf(wy1, bzw.x, wy0 * azw.x);
    r.w = fmaf(wy1, bzw.y, wy0 * azw.y);
    return r;
}

struct Setup {
    int e0, e1;        // table entries for this lane's z-slice (x0, x1 cells)
    float fx, fy, wz;  // wz = this lane's z weight
};

__device__ __forceinline__ Setup make_setup(float px, float py, float pz, int q)
{
    px = fminf(fmaxf(px * (float)NB, 0.0f), (float)(NB - 1));
    py = fminf(fmaxf(py * (float)NB, 0.0f), (float)(NB - 1));
    pz = fminf(fmaxf(pz * (float)NB, 0.0f), (float)(NB - 1));

    int ix0 = (int)floorf(px);
    int iy0 = (int)floorf(py);
    int iz0 = (int)floorf(pz);

    Setup s;
    s.fx = px - (float)ix0;
    s.fy = py - (float)iy0;
    float fz = pz - (float)iz0;
    s.wz = q ? fz : (1.0f - fz);

    int ix1 = min(ix0 + 1, NB - 1);
    int izq = min(iz0 + q, NB - 1);

    s.e0 = (ix0 * NB + iy0) * NB + izq;
    s.e1 = (ix1 * NB + iy0) * NB + izq;
    return s;
}

// Partial result for this lane's z-slice (all 4 channels, weighted by wz).
__device__ __forceinline__ float4 lane_partial(uint4 A, uint4 B, const Setup& s)
{
    float wy1 = s.fy, wy0 = 1.0f - s.fy;
    float4 m0 = ylerp(A, wy0, wy1);
    float4 m1 = ylerp(B, wy0, wy1);

    float wx1 = s.fx, wx0 = 1.0f - s.fx;
    float4 r;
    r.x = s.wz * fmaf(wx1, m1.x, wx0 * m0.x);
    r.y = s.wz * fmaf(wx1, m1.y, wx0 * m0.y);
    r.z = s.wz * fmaf(wx1, m1.z, wx0 * m0.z);
    r.w = s.wz * fmaf(wx1, m1.w, wx0 * m0.w);
    return r;
}

// Half-exchange: lane0 finalizes {x,y}, lane1 finalizes {z,w}; 2 shfls/point.
__device__ __forceinline__ float2 reduce_half(float4 r, int q)
{
    float s1 = __shfl_xor_sync(0xFFFFFFFFu, q ? r.x : r.z, 1);
    float s2 = __shfl_xor_sync(0xFFFFFFFFu, q ? r.y : r.w, 1);
    float2 o;
    if (q == 0) { o.x = r.x + s1; o.y = r.y + s2; }
    else        { o.x = r.z + s1; o.y = r.w + s2; }
    return o;
}

// 2 lanes per point, 2 points per lane-pair (p and p+half) -> 4 gathers in flight.
__global__ __launch_bounds__(256)
void interp_coop2_kernel(const float* __restrict__ x,
                         float2* __restrict__ out,   // [N,4] viewed as float2[2N]
                         int n, int half)
{
    int tid = blockIdx.x * blockDim.x + threadIdx.x;
    int p0  = tid >> 1;
    int q   = tid & 1;

    if (p0 >= half) return;
    int p1 = p0 + half;
    bool hasB = (p1 < n);
    int p1c = hasB ? p1 : p0;

    unsigned long long pol = make_evict_last_policy();

    // Streaming loads (evict-first): don't displace the pinned table in L2.
    float ax = __ldcs(&x[3 * p0 + 0]);
    float ay = __ldcs(&x[3 * p0 + 1]);
    float az = __ldcs(&x[3 * p0 + 2]);
    float bx = __ldcs(&x[3 * p1c + 0]);
    float by = __ldcs(&x[3 * p1c + 1]);
    float bz = __ldcs(&x[3 * p1c + 2]);

    Setup SA = make_setup(ax, ay, az, q);
    Setup SB = make_setup(bx, by, bz, q);

    // 4 gathers back-to-back; lane pairs hit 1 line per point per instruction.
    uint4 A0 = ldg_pin(&g_ypairs[SA.e0], pol);
    uint4 A1 = ldg_pin(&g_ypairs[SA.e1], pol);
    uint4 B0 = ldg_pin(&g_ypairs[SB.e0], pol);
    uint4 B1 = ldg_pin(&g_ypairs[SB.e1], pol);

    float4 ra = lane_partial(A0, A1, SA);
    float4 rb = lane_partial(B0, B1, SB);

    float2 oa = reduce_half(ra, q);
    float2 ob = reduce_half(rb, q);

    __stcs(&out[2 * p0 + q], oa);          // streaming store, pair writes 16B
    if (hasB)
        __stcs(&out[2 * p1 + q], ob);
}

extern "C" void kernel_launch(void* const* d_in, const int* in_sizes, int n_in,
                              void* d_out, int out_size)
{
    const float*  x    = (const float*)d_in[0];   // [N,3] float32
    const float4* grid = (const float4*)d_in[1];  // [128,128,128,4] float32
    float2*       out  = (float2*)d_out;          // [N,4] float32

    int n = in_sizes[0] / 3;
    int half = (n + 1) / 2;

    const int block = 256;
    build_ypairs_kernel<<<(NB3 + block - 1) / block, block>>>(grid);

    long long threads = 2LL * half;
    int grid_dim = (int)((threads + block - 1) / block);
    interp_coop2_kernel<<<grid_dim, block>>>(x, out, n, half);
}

// round 12
// speedup vs baseline: 1.0548x; 1.0548x over previous
#include <cuda_runtime.h>
#include <cuda_fp16.h>

#define NB 128
#define NB3 (NB * NB * NB)

// y-pair table: P[ix][iy][iz] = { G(ix,iy,iz) 4xfp16, G(ix,min(iy+1,127),iz) 4xfp16 }
// 16 B/entry, 33.5 MB -> L2-resident. z-neighbors are ADJACENT entries, so a
// lane pair covering (iz0, iz0+1) hits one 128B line per instruction.
__device__ uint4 g_ypairs[NB3];

__device__ __forceinline__ uint2 pack_h4(float4 v)
{
    __half2 h0 = __floats2half2_rn(v.x, v.y);
    __half2 h1 = __floats2half2_rn(v.z, v.w);
    uint2 r;
    r.x = *reinterpret_cast<const unsigned int*>(&h0);
    r.y = *reinterpret_cast<const unsigned int*>(&h1);
    return r;
}

__global__ __launch_bounds__(256)
void build_ypairs_kernel(const float4* __restrict__ grid)
{
    int idx = blockIdx.x * blockDim.x + threadIdx.x;
    if (idx >= NB3) return;

    int iy = (idx >> 7) & (NB - 1);
    int dy = (iy < NB - 1) ? NB : 0;

    float4 a = grid[idx];        // (ix, iy,   iz)
    float4 b = grid[idx + dy];   // (ix, iy+1, iz) clamped; L2-hit via block locality

    uint2 pa = pack_h4(a);
    uint2 pb = pack_h4(b);

    uint4 v;
    v.x = pa.x; v.y = pa.y; v.z = pb.x; v.w = pb.y;
    g_ypairs[idx] = v;
}

// y-lerp of one entry: corner_y0*wy0 + corner_y1*wy1
__device__ __forceinline__ float4 ylerp(uint4 p, float wy0, float wy1)
{
    float2 axy = __half22float2(*reinterpret_cast<const __half2*>(&p.x));
    float2 azw = __half22float2(*reinterpret_cast<const __half2*>(&p.y));
    float2 bxy = __half22float2(*reinterpret_cast<const __half2*>(&p.z));
    float2 bzw = __half22float2(*reinterpret_cast<const __half2*>(&p.w));

    float4 r;
    r.x = fmaf(wy1, bxy.x, wy0 * axy.x);
    r.y = fmaf(wy1, bxy.y, wy0 * axy.y);
    r.z = fmaf(wy1, bzw.x, wy0 * azw.x);
    r.w = fmaf(wy1, bzw.y, wy0 * azw.y);
    return r;
}

struct Setup {
    int e0, e1;        // table entries for this lane's z-slice (x0, x1 cells)
    float fx, fy, wz;  // wz = this lane's z weight
};

__device__ __forceinline__ Setup make_setup(float px, float py, float pz, int q)
{
    px = fminf(fmaxf(px * (float)NB, 0.0f), (float)(NB - 1));
    py = fminf(fmaxf(py * (float)NB, 0.0f), (float)(NB - 1));
    pz = fminf(fmaxf(pz * (float)NB, 0.0f), (float)(NB - 1));

    int ix0 = (int)floorf(px);
    int iy0 = (int)floorf(py);
    int iz0 = (int)floorf(pz);

    Setup s;
    s.fx = px - (float)ix0;
    s.fy = py - (float)iy0;
    float fz = pz - (float)iz0;
    s.wz = q ? fz : (1.0f - fz);

    int ix1 = min(ix0 + 1, NB - 1);
    int izq = min(iz0 + q, NB - 1);

    s.e0 = (ix0 * NB + iy0) * NB + izq;
    s.e1 = (ix1 * NB + iy0) * NB + izq;
    return s;
}

// Partial result for this lane's z-slice (all 4 channels, weighted by wz).
__device__ __forceinline__ float4 lane_partial(uint4 A, uint4 B, const Setup& s)
{
    float wy1 = s.fy, wy0 = 1.0f - s.fy;
    float4 m0 = ylerp(A, wy0, wy1);
    float4 m1 = ylerp(B, wy0, wy1);

    float wx1 = s.fx, wx0 = 1.0f - s.fx;
    float4 r;
    r.x = s.wz * fmaf(wx1, m1.x, wx0 * m0.x);
    r.y = s.wz * fmaf(wx1, m1.y, wx0 * m0.y);
    r.z = s.wz * fmaf(wx1, m1.z, wx0 * m0.z);
    r.w = s.wz * fmaf(wx1, m1.w, wx0 * m0.w);
    return r;
}

// Half-exchange: lane0 finalizes {x,y}, lane1 finalizes {z,w}; 2 shfls/point.
__device__ __forceinline__ float2 reduce_half(float4 r, int q)
{
    float s1 = __shfl_xor_sync(0xFFFFFFFFu, q ? r.x : r.z, 1);
    float s2 = __shfl_xor_sync(0xFFFFFFFFu, q ? r.y : r.w, 1);
    float2 o;
    if (q == 0) { o.x = r.x + s1; o.y = r.y + s2; }
    else        { o.x = r.z + s1; o.y = r.w + s2; }
    return o;
}

// 2 lanes per point, 2 points per lane-pair (p and p+half) -> 4 gathers in flight.
__global__ __launch_bounds__(256)
void interp_coop2_kernel(const float* __restrict__ x,
                         float2* __restrict__ out,   // [N,4] viewed as float2[2N]
                         int n, int half)
{
    int tid = blockIdx.x * blockDim.x + threadIdx.x;
    int p0  = tid >> 1;
    int q   = tid & 1;

    if (p0 >= half) return;
    int p1 = p0 + half;
    bool hasB = (p1 < n);
    int p1c = hasB ? p1 : p0;

    // Streaming loads for the point coords (touched once).
    float ax = __ldcs(&x[3 * p0 + 0]);
    float ay = __ldcs(&x[3 * p0 + 1]);
    float az = __ldcs(&x[3 * p0 + 2]);
    float bx = __ldcs(&x[3 * p1c + 0]);
    float by = __ldcs(&x[3 * p1c + 1]);
    float bz = __ldcs(&x[3 * p1c + 2]);

    Setup SA = make_setup(ax, ay, az, q);
    Setup SB = make_setup(bx, by, bz, q);

    // Gathers bypass L1 allocation (__ldcg, L2-only): random 32B windows into a
    // 33.5MB table never hit the 228KB L1, and skipping the fill-write halves
    // L1tex wavefront work per miss. Lane pairs still hit 1 line per instruction.
    uint4 A0 = __ldcg(&g_ypairs[SA.e0]);
    uint4 A1 = __ldcg(&g_ypairs[SA.e1]);
    uint4 B0 = __ldcg(&g_ypairs[SB.e0]);
    uint4 B1 = __ldcg(&g_ypairs[SB.e1]);

    float4 ra = lane_partial(A0, A1, SA);
    float4 rb = lane_partial(B0, B1, SB);

    float2 oa = reduce_half(ra, q);
    float2 ob = reduce_half(rb, q);

    __stcs(&out[2 * p0 + q], oa);          // streaming store, pair writes 16B
    if (hasB)
        __stcs(&out[2 * p1 + q], ob);
}

extern "C" void kernel_launch(void* const* d_in, const int* in_sizes, int n_in,
                              void* d_out, int out_size)
{
    const float*  x    = (const float*)d_in[0];   // [N,3] float32
    const float4* grid = (const float4*)d_in[1];  // [128,128,128,4] float32
    float2*       out  = (float2*)d_out;          // [N,4] float32

    int n = in_sizes[0] / 3;
    int half = (n + 1) / 2;

    const int block = 256;
    build_ypairs_kernel<<<(NB3 + block - 1) / block, block>>>(grid);

    long long threads = 2LL * half;
    int grid_dim = (int)((threads + block - 1) / block);
    interp_coop2_kernel<<<grid_dim, block>>>(x, out, n, half);
}